// round 11
// baseline (speedup 1.0000x reference)
#include <cuda_runtime.h>
#include <stdint.h>
#include <math.h>

#define BB 4
#define CC 256
#define LLEN 4096
#define NN 16
#define EPSF 1e-7f
#define OUT_MAIN (BB*CC*LLEN)

__device__ float g_xr [BB*CC*LLEN];
__device__ float g_xo [BB*CC*LLEN];
__device__ float g_att[BB*NN*LLEN];
__device__ float g_fpos[BB*CC*NN];
__device__ float g_P[BB*CC*NN];
__device__ float g_Q[BB*CC*NN];
__device__ float g_cnt[BB*NN];
__device__ int   g_idx1[BB*32];
__device__ int   g_idx2[BB*32];

// ---------- Threefry-2x32-20 ----------
__device__ __forceinline__ uint32_t rotl32(uint32_t v,int r){return (v<<r)|(v>>(32-r));}
__device__ __forceinline__ void tf2x32(uint32_t k0,uint32_t k1,uint32_t x0,uint32_t x1,
                                       uint32_t&o0,uint32_t&o1){
  uint32_t ks2=k0^k1^0x1BD11BDAu;
  x0+=k0; x1+=k1;
#define TFR(r) { x0+=x1; x1=rotl32(x1,r); x1^=x0; }
  TFR(13)TFR(15)TFR(26)TFR(6)  x0+=k1;  x1+=ks2+1u;
  TFR(17)TFR(29)TFR(16)TFR(24) x0+=ks2; x1+=k0+2u;
  TFR(13)TFR(15)TFR(26)TFR(6)  x0+=k0;  x1+=k1+3u;
  TFR(17)TFR(29)TFR(16)TFR(24) x0+=k1;  x1+=ks2+4u;
  TFR(13)TFR(15)TFR(26)TFR(6)  x0+=ks2; x1+=k0+5u;
#undef TFR
  o0=x0; o1=x1;
}
__device__ __forceinline__ void jax_subkeys(uint32_t*r1,uint32_t*r2,uint32_t*r3){
  uint32_t a0,a1,b0,b1,c0,c1;
  tf2x32(0u,42u,0u,3u,a0,a1);
  tf2x32(0u,42u,1u,4u,b0,b1);
  tf2x32(0u,42u,2u,5u,c0,c1);
  r1[0]=a0; r1[1]=b0;  r2[0]=c0; r2[1]=a1;  r3[0]=b1; r3[1]=c1;
}
__device__ __forceinline__ float gumbel_bits(uint32_t bits){
  float f=__uint_as_float((bits>>9)|0x3f800000u)-1.0f;
  float u=fmaxf(1e-20f, f*(1.0f-1e-20f)+1e-20f);
  return -__logf(-__logf(u));
}

// ---------- gumbel top-32: per-thread sorted lists + head-tournament ----------
__global__ void __launch_bounds__(256) k_sample(const float* __restrict__ mask,
                                                int pass, int* __restrict__ outbase){
  int b=blockIdx.x, tid=threadIdx.x, lane=tid&31, wid=tid>>5;
  uint32_t r1[2],r2[2],r3[2]; jax_subkeys(r1,r2,r3);
  const uint32_t* key = pass?r2:r1;
  unsigned long long lst[16];
#pragma unroll 1
  for(int i=0;i<16;i++){
    int l=i*256+tid;
    int j=b*LLEN+l;
    uint32_t ii=(uint32_t)(j&8191),o0,o1;
    tf2x32(key[0],key[1],ii,ii+8192u,o0,o1);
    uint32_t bits=(j<8192)?o0:o1;
    float wv=mask[j]; if(pass) wv=1.0f-wv;
    float scv=__logf(wv+1e-20f)+gumbel_bits(bits);
    uint32_t fb=__float_as_uint(scv);
    uint32_t u=(fb&0x80000000u)?(~fb):(fb|0x80000000u);
    unsigned long long k=((unsigned long long)u<<32)|(uint32_t)(LLEN-1-l);
    int jj=i;
    while(jj>0 && lst[jj-1]<k){ lst[jj]=lst[jj-1]; jj--; }
    lst[jj]=k;
  }
  __shared__ unsigned long long wred[8];
  __shared__ unsigned long long winS;
  unsigned long long cur=lst[0]; int p=0;
  int* outI = outbase + b*32;
  for(int j=0;j<32;j++){
    unsigned long long v=cur;
#pragma unroll
    for(int o=16;o;o>>=1){
      unsigned long long t=__shfl_xor_sync(0xffffffffu,v,o);
      if(t>v)v=t;
    }
    if(lane==0) wred[wid]=v;
    __syncthreads();
    if(tid==0){
      unsigned long long m=wred[0];
#pragma unroll
      for(int q=1;q<8;q++) if(wred[q]>m)m=wred[q];
      winS=m;
      outI[j]=LLEN-1-(int)(m&0xffffffffu);
    }
    __syncthreads();
    if(cur==winS){ p++; cur=(p<16)?lst[p]:0ull; }
  }
}

// ---------- orth loss (4-way accum) + zero g_cnt ----------
__global__ void __launch_bounds__(256) k_orth(const float* __restrict__ kn,
                                              float* __restrict__ out_loss){
  __shared__ float ks[NN][260];
  __shared__ float sym[NN][17];
  __shared__ float red[256];
  int tid=threadIdx.x;
  if(tid<BB*NN) g_cnt[tid]=0.f;
  for(int i=tid;i<NN*CC;i+=256) ks[i>>8][i&255]=kn[i];
  __syncthreads();
  int i=tid>>4, j=tid&15;
  float s0=0.f,s1=0.f,s2=0.f,s3=0.f;
#pragma unroll 4
  for(int c=0;c<CC;c+=4){
    s0=fmaf(ks[i][c  ],ks[j][c  ],s0);
    s1=fmaf(ks[i][c+1],ks[j][c+1],s1);
    s2=fmaf(ks[i][c+2],ks[j][c+2],s2);
    s3=fmaf(ks[i][c+3],ks[j][c+3],s3);
  }
  float s=(s0+s1)+(s2+s3);
  sym[i][j]=s; __syncthreads();
  float l=sym[i][j]/(sqrtf(sym[i][i])*sqrtf(sym[j][j])+EPSF)-((i==j)?1.0f:0.0f);
  red[tid]=l*l; __syncthreads();
  for(int sh=128;sh;sh>>=1){ if(tid<sh) red[tid]+=red[tid+sh]; __syncthreads(); }
  if(tid==0) *out_loss = 0.001f*logf(red[0]+1.0f);
}

// ---------- tf32 dual GEMM (launch #4 -> profiled) ----------
#define GM 128
#define GN 64
#define GK 16
__device__ __forceinline__ void mma_tf32(float* c, const uint32_t* a, const uint32_t* b){
  asm volatile(
    "mma.sync.aligned.m16n8k8.row.col.f32.tf32.tf32.f32 "
    "{%0,%1,%2,%3}, {%4,%5,%6,%7}, {%8,%9}, {%0,%1,%2,%3};"
    : "+f"(c[0]),"+f"(c[1]),"+f"(c[2]),"+f"(c[3])
    : "r"(a[0]),"r"(a[1]),"r"(a[2]),"r"(a[3]), "r"(b[0]),"r"(b[1]));
}
#define ASI(buf,w,m,k) dsm[(((buf)*2+(w))*GM+(m))*20+(k)]
#define BSI(buf,k,n)   dsm[10240+((buf)*GK+(k))*72+(n)]
__global__ void __launch_bounds__(256) k_gemm_dual(
    const float* __restrict__ W0,const float* __restrict__ b0,
    const float* __restrict__ W1,const float* __restrict__ b1,
    const float* __restrict__ X, float* __restrict__ Y0, float* __restrict__ Y1){
  extern __shared__ float dsm[];
  int b=blockIdx.z;
  const float* Xb=X+(size_t)b*CC*LLEN;
  int m0=blockIdx.y*GM, l0=blockIdx.x*GN, tid=threadIdx.x;
  int wid=tid>>5, lane=tid&31;
  int wm=(wid&3)*32, wn=(wid>>2)*32;
  int gid=lane>>2, tig=lane&3;
  int aRow=tid>>2, aKc=(tid&3)<<2;
  int bKr=tid>>4, bNc=(tid&15)<<2;
  const float* w0a=W0+(size_t)(m0+aRow)*CC+aKc;
  const float* w0b=W0+(size_t)(m0+aRow+64)*CC+aKc;
  const float* w1a=W1+(size_t)(m0+aRow)*CC+aKc;
  const float* w1b=W1+(size_t)(m0+aRow+64)*CC+aKc;
  float acc[2][2][4][4];
#pragma unroll
  for(int w=0;w<2;w++)
#pragma unroll
    for(int i=0;i<2;i++)
#pragma unroll
      for(int j=0;j<4;j++)
#pragma unroll
        for(int k=0;k<4;k++) acc[w][i][j][k]=0.f;

  *(float4*)&ASI(0,0,aRow,aKc)   =*(const float4*)(w0a);
  *(float4*)&ASI(0,0,aRow+64,aKc)=*(const float4*)(w0b);
  *(float4*)&ASI(0,1,aRow,aKc)   =*(const float4*)(w1a);
  *(float4*)&ASI(0,1,aRow+64,aKc)=*(const float4*)(w1b);
  *(float4*)&BSI(0,bKr,bNc)      =*(const float4*)(Xb+(size_t)bKr*LLEN+l0+bNc);
  __syncthreads();

  float4 p00,p01,p10,p11,pb;
  for(int kt=0;kt<CC/GK;kt++){
    int cur=kt&1;
    if(kt<CC/GK-1){
      int k0=(kt+1)*GK;
      p00=*(const float4*)(w0a+k0); p01=*(const float4*)(w0b+k0);
      p10=*(const float4*)(w1a+k0); p11=*(const float4*)(w1b+k0);
      pb =*(const float4*)(Xb+(size_t)(k0+bKr)*LLEN+l0+bNc);
    }
#pragma unroll
    for(int ks=0;ks<GK;ks+=8){
      uint32_t af[2][2][4], bf[4][2];
#pragma unroll
      for(int w=0;w<2;w++)
#pragma unroll
        for(int mt=0;mt<2;mt++){
          int m=wm+mt*16+gid;
          af[w][mt][0]=__float_as_uint(ASI(cur,w,m  ,ks+tig  ));
          af[w][mt][1]=__float_as_uint(ASI(cur,w,m+8,ks+tig  ));
          af[w][mt][2]=__float_as_uint(ASI(cur,w,m  ,ks+tig+4));
          af[w][mt][3]=__float_as_uint(ASI(cur,w,m+8,ks+tig+4));
        }
#pragma unroll
      for(int nt=0;nt<4;nt++){
        int n=wn+nt*8+gid;
        bf[nt][0]=__float_as_uint(BSI(cur,ks+tig  ,n));
        bf[nt][1]=__float_as_uint(BSI(cur,ks+tig+4,n));
      }
#pragma unroll
      for(int w=0;w<2;w++)
#pragma unroll
        for(int mt=0;mt<2;mt++)
#pragma unroll
          for(int nt=0;nt<4;nt++)
            mma_tf32(acc[w][mt][nt], af[w][mt], bf[nt]);
    }
    if(kt<CC/GK-1){
      int nxt=cur^1;
      *(float4*)&ASI(nxt,0,aRow,aKc)   =p00;
      *(float4*)&ASI(nxt,0,aRow+64,aKc)=p01;
      *(float4*)&ASI(nxt,1,aRow,aKc)   =p10;
      *(float4*)&ASI(nxt,1,aRow+64,aKc)=p11;
      *(float4*)&BSI(nxt,bKr,bNc)      =pb;
    }
    __syncthreads();
  }
#pragma unroll
  for(int w=0;w<2;w++){
    const float* bias = w ? b1 : b0;
    float* Yb = (w ? Y1 : Y0) + (size_t)b*CC*LLEN;
#pragma unroll
    for(int mt=0;mt<2;mt++){
      int row=m0+wm+mt*16+gid;
      float bv0=bias[row], bv8=bias[row+8];
#pragma unroll
      for(int nt=0;nt<4;nt++){
        int col=l0+wn+nt*8+2*tig;
        float2 v0={acc[w][mt][nt][0]+bv0, acc[w][mt][nt][1]+bv0};
        float2 v8={acc[w][mt][nt][2]+bv8, acc[w][mt][nt][3]+bv8};
        *(float2*)(Yb+(size_t)row*LLEN+col)=v0;
        *(float2*)(Yb+(size_t)(row+8)*LLEN+col)=v8;
      }
    }
  }
}

// ---------- fused: gather cols + fsa_sel GEMM (coalesced W staging) + selection ----------
// dsm: fcols[256*36] | xcols[256*36] | fsel[256*36] | ws[32*257]  = 143488 B
__global__ void __launch_bounds__(256) k_select(const float* __restrict__ f,
                                                const float* __restrict__ ksa_w,
                                                const float* __restrict__ ksa_b){
  extern __shared__ float sm[];
  float* fcols=sm;
  float* xcols=sm+9216;
  float* fsel =sm+18432;
  float* ws   =sm+27648;
  __shared__ float rel[1024];
  __shared__ float nf[32],nx[32],f2[32];
  __shared__ int im[32],ik[32],selm[NN];
  int b=blockIdx.x, tid=threadIdx.x;
  if(tid<32){ im[tid]=g_idx1[b*32+tid]; ik[tid]=g_idx2[b*32+tid]; }
  __syncthreads();
  for(int i=tid;i<256*32;i+=256){
    int c=i>>5, j=i&31;
    fcols[c*36+j]=f   [((size_t)b*CC+c)*LLEN+im[j]];
    xcols[c*36+j]=g_xr[((size_t)b*CC+c)*LLEN+ik[j]];
  }
  __syncthreads();
  {
    int m=tid;
    float acc[32];
#pragma unroll
    for(int j=0;j<32;j++) acc[j]=0.f;
    for(int c0=0;c0<CC;c0+=32){
      __syncthreads();
      for(int i=tid;i<256*32;i+=256){
        int mr=i>>5, cj=i&31;
        ws[cj*257+mr]=ksa_w[(size_t)mr*CC+c0+cj];
      }
      __syncthreads();
#pragma unroll 1
      for(int cj=0;cj<32;cj++){
        float w=ws[cj*257+m];
        const float* fr=&fcols[(c0+cj)*36];
#pragma unroll
        for(int q=0;q<8;q++){
          float4 v=*(const float4*)(fr+q*4);
          acc[q*4+0]=fmaf(w,v.x,acc[q*4+0]);
          acc[q*4+1]=fmaf(w,v.y,acc[q*4+1]);
          acc[q*4+2]=fmaf(w,v.z,acc[q*4+2]);
          acc[q*4+3]=fmaf(w,v.w,acc[q*4+3]);
        }
      }
    }
    float bv=ksa_b[m];
#pragma unroll
    for(int j=0;j<32;j++) fsel[m*36+j]=acc[j]+bv;
  }
  __syncthreads();
  if(tid<64){
    int j=tid&31;
    const float* base=(tid<32)?fsel:xcols;
    float s=0.f;
    for(int c=0;c<CC;c++){ float v=base[c*36+j]; s=fmaf(v,v,s); }
    if(tid<32) nf[j]=sqrtf(s); else nx[j]=sqrtf(s);
  }
  for(int p=tid;p<1024;p+=256){
    int m=p>>5, k=p&31;
    float s=0.f;
#pragma unroll 4
    for(int c=0;c<CC;c++) s=fmaf(fsel[c*36+m],xcols[c*36+k],s);
    rel[p]=s;
  }
  __syncthreads();
  if(tid<32){
    float mx=-INFINITY;
    for(int k=0;k<32;k++) mx=fmaxf(mx, rel[tid*32+k]/(nf[tid]*nx[k]+EPSF));
    f2[tid]=mx;
  }
  __syncthreads();
  if(tid==0){
    float mx=-INFINITY;
    for(int m=0;m<32;m++) mx=fmaxf(mx,f2[m]);
    float s=0.f;
    for(int m=0;m<32;m++){ f2[m]=__expf(f2[m]-mx); s+=f2[m]; }
    uint32_t r1k[2],r2k[2],r3k[2]; jax_subkeys(r1k,r2k,r3k);
    for(int m=0;m<32;m++){
      int j=b*32+m;
      uint32_t i=(uint32_t)(j&63),o0,o1;
      tf2x32(r3k[0],r3k[1],i,i+64u,o0,o1);
      uint32_t bits=(j<64)?o0:o1;
      f2[m]=__logf(f2[m]/s+1e-20f)+gumbel_bits(bits);
    }
    for(int j=0;j<NN;j++){
      float bv=-INFINITY; int bi=0;
      for(int m=0;m<32;m++) if(f2[m]>bv){bv=f2[m];bi=m;}
      selm[j]=bi; f2[bi]=-INFINITY;
    }
  }
  __syncthreads();
  {
    int c=tid;
#pragma unroll
    for(int j=0;j<NN;j++)
      g_fpos[((size_t)b*CC+c)*NN+j]=fsel[c*36+selm[j]];
  }
}

// ---------- fused act_pos + xn + softmax + cnt atomics ----------
__global__ void __launch_bounds__(128) k_att(const float* __restrict__ x,
                                             const float* __restrict__ kn,
                                             const float* __restrict__ alpha){
  __shared__ float fp_s[CC*NN];
  __shared__ float kn_s[CC*NN];
  __shared__ float al_s[NN];
  int b=blockIdx.y, tid=threadIdx.x, lane=tid&31;
  int l=blockIdx.x*128+tid;
  for(int i=tid;i<CC*NN;i+=128){
    fp_s[i]=g_fpos[(size_t)b*CC*NN+i];
    int c=i>>4, n=i&15;
    kn_s[i]=kn[n*CC+c];
  }
  if(tid<NN) al_s[tid]=fminf(fmaxf(alpha[tid],0.0f),1.0f);
  __syncthreads();
  float aa[NN],ax[NN];
#pragma unroll
  for(int n=0;n<NN;n++){aa[n]=0.f;ax[n]=0.f;}
  const float* xrp=g_xr+(size_t)b*CC*LLEN+l;
  const float* xp =x   +(size_t)b*CC*LLEN+l;
  for(int c=0;c<CC;c++){
    float xrv=__ldg(xrp+(size_t)c*LLEN);
    float xv =__ldg(xp +(size_t)c*LLEN);
    const float* fr=fp_s+c*NN;
    const float* kr=kn_s+c*NN;
#pragma unroll
    for(int n=0;n<NN;n++){
      aa[n]=fmaf(xrv,fr[n],aa[n]);
      ax[n]=fmaf(xv ,kr[n],ax[n]);
    }
  }
  float lg[NN],mx=-INFINITY;
#pragma unroll
  for(int n=0;n<NN;n++){ lg[n]=(al_s[n]*aa[n]+ax[n])*0.1f; mx=fmaxf(mx,lg[n]); }
  float s=0.f;
#pragma unroll
  for(int n=0;n<NN;n++){ lg[n]=__expf(lg[n]-mx); s+=lg[n]; }
  float inv=1.0f/s;
#pragma unroll
  for(int n=0;n<NN;n++){
    float v=lg[n]*inv;
    g_att[((size_t)b*NN+n)*LLEN+l]=v;
#pragma unroll
    for(int o=16;o;o>>=1) v+=__shfl_xor_sync(0xffffffffu,v,o);
    if(lane==0) atomicAdd(&g_cnt[b*NN+n], v);
  }
}

// ---------- per-(b,c,n) weighted moments (c-tile 8, 128 blocks/batch) ----------
__global__ void __launch_bounds__(128) k_stats(){
  __shared__ float att_s[NN][130];
  __shared__ float xo_s[8][130];
  int b=blockIdx.y, c0=blockIdx.x*8, tid=threadIdx.x;
  int cr=tid>>4, n=tid&15;
  float s1=0.f,s2=0.f;
  for(int l0=0;l0<LLEN;l0+=128){
    for(int i=tid;i<16*128;i+=128){
      int r=i>>7, lc=i&127;
      att_s[r][lc]=g_att[((size_t)b*NN+r)*LLEN+l0+lc];
    }
    for(int i=tid;i<8*128;i+=128){
      int r=i>>7, lc=i&127;
      xo_s[r][lc]=g_xo[((size_t)b*CC+c0+r)*LLEN+l0+lc];
    }
    __syncthreads();
#pragma unroll 4
    for(int lc=0;lc<128;lc+=2){
      float2 xv=*(float2*)&xo_s[cr][lc];
      float2 av=*(float2*)&att_s[n][lc];
      float h0=xv.x*av.x, h1=xv.y*av.y;
      s1+=h0+h1; s2=fmaf(h0,h0,fmaf(h1,h1,s2));
    }
    __syncthreads();
  }
  float cnt=g_cnt[b*NN+n]+EPSF;
  float mean=s1/cnt;
  float varsum=fmaf((float)LLEN*mean,mean, s2-2.0f*mean*s1);
  float stdv=sqrtf(fmaxf(varsum,0.0f)/cnt);
  float p=1.0f/(stdv+EPSF);
  size_t o=((size_t)b*CC+c0+cr)*NN+n;
  g_P[o]=p; g_Q[o]=mean*p;
}

// ---------- fused K=16 GEMMs + epilogue ----------
__global__ void __launch_bounds__(256) k_fuse(const float* __restrict__ x,
                                              const float* __restrict__ sigma,
                                              float* __restrict__ out){
  __shared__ float att_s[NN][64];
  __shared__ float P_s[16][16], Q_s[16][16];
  int b=blockIdx.z, c0=blockIdx.y*16, l0=blockIdx.x*64;
  int tid=threadIdx.x;
  for(int i=tid;i<NN*64;i+=256){
    int n=i>>6, l=i&63;
    att_s[n][l]=g_att[((size_t)b*NN+n)*LLEN+l0+l];
  }
  {
    int cl=tid>>4, n=tid&15;
    P_s[cl][n]=g_P[((size_t)b*CC+c0+cl)*NN+n];
    Q_s[cl][n]=g_Q[((size_t)b*CC+c0+cl)*NN+n];
  }
  __syncthreads();
  float sg=sigma[0];
  int ll=tid&63, cbase=tid>>6;
  for(int cc=cbase;cc<16;cc+=4){
    float r=0.f,s=0.f;
#pragma unroll
    for(int n=0;n<NN;n++){
      float a=att_s[n][ll];
      r=fmaf(P_s[cc][n],a,r);
      s=fmaf(Q_s[cc][n],a,s);
    }
    size_t o=((size_t)b*CC+c0+cc)*LLEN+l0+ll;
    out[o]=x[o]+sg*(g_xo[o]*r-s);
  }
}

extern "C" void kernel_launch(void* const* d_in, const int* in_sizes, int n_in,
                              void* d_out, int out_size){
  const float* x    =(const float*)d_in[0];
  const float* f    =(const float*)d_in[1];
  const float* mask =(const float*)d_in[2];
  const float* ksa_w=(const float*)d_in[3];
  const float* ksa_b=(const float*)d_in[4];
  const float* kr_w =(const float*)d_in[5];
  const float* kr_b =(const float*)d_in[6];
  const float* kn   =(const float*)d_in[7];
  const float* ko_w =(const float*)d_in[8];
  const float* ko_b =(const float*)d_in[9];
  const float* alpha=(const float*)d_in[10];
  const float* sigma=(const float*)d_in[11];
  float* out=(float*)d_out;

  float *xr,*xo;
  int *idx1,*idx2;
  cudaGetSymbolAddress((void**)&xr ,g_xr);
  cudaGetSymbolAddress((void**)&xo ,g_xo);
  cudaGetSymbolAddress((void**)&idx1,g_idx1);
  cudaGetSymbolAddress((void**)&idx2,g_idx2);

  cudaFuncSetAttribute(k_gemm_dual, cudaFuncAttributeMaxDynamicSharedMemorySize, 50176);
  cudaFuncSetAttribute(k_select,    cudaFuncAttributeMaxDynamicSharedMemorySize, 143488);

  // launch order chosen so k_gemm_dual is the 4th kernel launch (ncu capture slot)
  k_sample<<<BB,256>>>(mask,0,idx1);
  k_sample<<<BB,256>>>(mask,1,idx2);
  k_orth<<<1,256>>>(kn, out+(out_size-1));
  dim3 gg(LLEN/GN, CC/GM, BB);
  k_gemm_dual<<<gg,256,50176>>>(kr_w,kr_b,ko_w,ko_b,x,xr,xo);
  k_select<<<BB,256,143488>>>(f,ksa_w,ksa_b);
  k_att<<<dim3(LLEN/128,BB),128>>>(x,kn,alpha);
  k_stats<<<dim3(CC/8,BB),128>>>();
  k_fuse<<<dim3(LLEN/64,CC/16,BB),256>>>(x,sigma,out);
}

// round 16
// speedup vs baseline: 1.4185x; 1.4185x over previous
#include <cuda_runtime.h>
#include <stdint.h>
#include <math.h>

#define BB 4
#define CC 256
#define LLEN 4096
#define NN 16
#define EPSF 1e-7f
#define OUT_MAIN (BB*CC*LLEN)

__device__ float g_xr [BB*CC*LLEN];
__device__ float g_xo [BB*CC*LLEN];
__device__ float g_att[BB*NN*LLEN];
__device__ float g_fpos[BB*CC*NN];
__device__ float g_P[BB*CC*NN];
__device__ float g_Q[BB*CC*NN];
__device__ float g_cnt[BB*NN];
__device__ int   g_idx1[BB*32];
__device__ int   g_idx2[BB*32];

// ---------- Threefry-2x32-20 ----------
__device__ __forceinline__ uint32_t rotl32(uint32_t v,int r){return (v<<r)|(v>>(32-r));}
__device__ __forceinline__ void tf2x32(uint32_t k0,uint32_t k1,uint32_t x0,uint32_t x1,
                                       uint32_t&o0,uint32_t&o1){
  uint32_t ks2=k0^k1^0x1BD11BDAu;
  x0+=k0; x1+=k1;
#define TFR(r) { x0+=x1; x1=rotl32(x1,r); x1^=x0; }
  TFR(13)TFR(15)TFR(26)TFR(6)  x0+=k1;  x1+=ks2+1u;
  TFR(17)TFR(29)TFR(16)TFR(24) x0+=ks2; x1+=k0+2u;
  TFR(13)TFR(15)TFR(26)TFR(6)  x0+=k0;  x1+=k1+3u;
  TFR(17)TFR(29)TFR(16)TFR(24) x0+=k1;  x1+=ks2+4u;
  TFR(13)TFR(15)TFR(26)TFR(6)  x0+=ks2; x1+=k0+5u;
#undef TFR
  o0=x0; o1=x1;
}
__device__ __forceinline__ void jax_subkeys(uint32_t*r1,uint32_t*r2,uint32_t*r3){
  uint32_t a0,a1,b0,b1,c0,c1;
  tf2x32(0u,42u,0u,3u,a0,a1);
  tf2x32(0u,42u,1u,4u,b0,b1);
  tf2x32(0u,42u,2u,5u,c0,c1);
  r1[0]=a0; r1[1]=b0;  r2[0]=c0; r2[1]=a1;  r3[0]=b1; r3[1]=c1;
}
__device__ __forceinline__ float gumbel_bits(uint32_t bits){
  float f=__uint_as_float((bits>>9)|0x3f800000u)-1.0f;
  float u=fmaxf(1e-20f, f*(1.0f-1e-20f)+1e-20f);
  return -__logf(-__logf(u));
}

// ---------- k_pre: blocks 0-7 = gumbel top-32 (b,pass); block 8 = orth + cnt zero ----------
__global__ void __launch_bounds__(256) k_pre(const float* __restrict__ mask,
                                             const float* __restrict__ kn,
                                             float* __restrict__ out_loss){
  __shared__ unsigned long long wred[8];
  __shared__ unsigned long long winS;
  __shared__ float ks[NN][260];
  __shared__ float sym[NN][17];
  __shared__ float red[256];
  int blk=blockIdx.x, tid=threadIdx.x;
  if(blk<8){
    int pass=blk>>2, b=blk&3;
    int lane=tid&31, wid=tid>>5;
    uint32_t r1[2],r2[2],r3[2]; jax_subkeys(r1,r2,r3);
    const uint32_t* key = pass?r2:r1;
    unsigned long long lst[16];
#pragma unroll 1
    for(int i=0;i<16;i++){
      int l=i*256+tid;
      int j=b*LLEN+l;
      uint32_t ii=(uint32_t)(j&8191),o0,o1;
      tf2x32(key[0],key[1],ii,ii+8192u,o0,o1);
      uint32_t bits=(j<8192)?o0:o1;
      float wv=mask[j]; if(pass) wv=1.0f-wv;
      float scv=__logf(wv+1e-20f)+gumbel_bits(bits);
      uint32_t fb=__float_as_uint(scv);
      uint32_t u=(fb&0x80000000u)?(~fb):(fb|0x80000000u);
      unsigned long long k=((unsigned long long)u<<32)|(uint32_t)(LLEN-1-l);
      int jj=i;
      while(jj>0 && lst[jj-1]<k){ lst[jj]=lst[jj-1]; jj--; }
      lst[jj]=k;
    }
    unsigned long long cur=lst[0]; int p=0;
    int* outI = (pass?g_idx2:g_idx1) + b*32;
    for(int j=0;j<32;j++){
      unsigned long long v=cur;
#pragma unroll
      for(int o=16;o;o>>=1){
        unsigned long long t=__shfl_xor_sync(0xffffffffu,v,o);
        if(t>v)v=t;
      }
      if(lane==0) wred[wid]=v;
      __syncthreads();
      if(tid==0){
        unsigned long long m=wred[0];
#pragma unroll
        for(int q=1;q<8;q++) if(wred[q]>m)m=wred[q];
        winS=m;
        outI[j]=LLEN-1-(int)(m&0xffffffffu);
      }
      __syncthreads();
      if(cur==winS){ p++; cur=(p<16)?lst[p]:0ull; }
    }
  }else{
    if(tid<BB*NN) g_cnt[tid]=0.f;
    for(int i=tid;i<NN*CC;i+=256) ks[i>>8][i&255]=kn[i];
    __syncthreads();
    int i=tid>>4, j=tid&15;
    float s0=0.f,s1=0.f,s2=0.f,s3=0.f;
#pragma unroll 4
    for(int c=0;c<CC;c+=4){
      s0=fmaf(ks[i][c  ],ks[j][c  ],s0);
      s1=fmaf(ks[i][c+1],ks[j][c+1],s1);
      s2=fmaf(ks[i][c+2],ks[j][c+2],s2);
      s3=fmaf(ks[i][c+3],ks[j][c+3],s3);
    }
    float s=(s0+s1)+(s2+s3);
    sym[i][j]=s; __syncthreads();
    float l=sym[i][j]/(sqrtf(sym[i][i])*sqrtf(sym[j][j])+EPSF)-((i==j)?1.0f:0.0f);
    red[tid]=l*l; __syncthreads();
    for(int sh=128;sh;sh>>=1){ if(tid<sh) red[tid]+=red[tid+sh]; __syncthreads(); }
    if(tid==0) *out_loss = 0.001f*logf(red[0]+1.0f);
  }
}

// ---------- tf32 dual GEMM ----------
#define GM 128
#define GN 64
#define GK 16
__device__ __forceinline__ void mma_tf32(float* c, const uint32_t* a, const uint32_t* b){
  asm volatile(
    "mma.sync.aligned.m16n8k8.row.col.f32.tf32.tf32.f32 "
    "{%0,%1,%2,%3}, {%4,%5,%6,%7}, {%8,%9}, {%0,%1,%2,%3};"
    : "+f"(c[0]),"+f"(c[1]),"+f"(c[2]),"+f"(c[3])
    : "r"(a[0]),"r"(a[1]),"r"(a[2]),"r"(a[3]), "r"(b[0]),"r"(b[1]));
}
#define ASI(buf,w,m,k) dsm[(((buf)*2+(w))*GM+(m))*20+(k)]
#define BSI(buf,k,n)   dsm[10240+((buf)*GK+(k))*72+(n)]
__global__ void __launch_bounds__(256) k_gemm_dual(
    const float* __restrict__ W0,const float* __restrict__ b0,
    const float* __restrict__ W1,const float* __restrict__ b1,
    const float* __restrict__ X, float* __restrict__ Y0, float* __restrict__ Y1){
  extern __shared__ float dsm[];
  int b=blockIdx.z;
  const float* Xb=X+(size_t)b*CC*LLEN;
  int m0=blockIdx.y*GM, l0=blockIdx.x*GN, tid=threadIdx.x;
  int wid=tid>>5, lane=tid&31;
  int wm=(wid&3)*32, wn=(wid>>2)*32;
  int gid=lane>>2, tig=lane&3;
  int aRow=tid>>2, aKc=(tid&3)<<2;
  int bKr=tid>>4, bNc=(tid&15)<<2;
  const float* w0a=W0+(size_t)(m0+aRow)*CC+aKc;
  const float* w0b=W0+(size_t)(m0+aRow+64)*CC+aKc;
  const float* w1a=W1+(size_t)(m0+aRow)*CC+aKc;
  const float* w1b=W1+(size_t)(m0+aRow+64)*CC+aKc;
  float acc[2][2][4][4];
#pragma unroll
  for(int w=0;w<2;w++)
#pragma unroll
    for(int i=0;i<2;i++)
#pragma unroll
      for(int j=0;j<4;j++)
#pragma unroll
        for(int k=0;k<4;k++) acc[w][i][j][k]=0.f;

  *(float4*)&ASI(0,0,aRow,aKc)   =*(const float4*)(w0a);
  *(float4*)&ASI(0,0,aRow+64,aKc)=*(const float4*)(w0b);
  *(float4*)&ASI(0,1,aRow,aKc)   =*(const float4*)(w1a);
  *(float4*)&ASI(0,1,aRow+64,aKc)=*(const float4*)(w1b);
  *(float4*)&BSI(0,bKr,bNc)      =*(const float4*)(Xb+(size_t)bKr*LLEN+l0+bNc);
  __syncthreads();

  float4 p00,p01,p10,p11,pb;
  for(int kt=0;kt<CC/GK;kt++){
    int cur=kt&1;
    if(kt<CC/GK-1){
      int k0=(kt+1)*GK;
      p00=*(const float4*)(w0a+k0); p01=*(const float4*)(w0b+k0);
      p10=*(const float4*)(w1a+k0); p11=*(const float4*)(w1b+k0);
      pb =*(const float4*)(Xb+(size_t)(k0+bKr)*LLEN+l0+bNc);
    }
#pragma unroll
    for(int ks=0;ks<GK;ks+=8){
      uint32_t af[2][2][4], bf[4][2];
#pragma unroll
      for(int w=0;w<2;w++)
#pragma unroll
        for(int mt=0;mt<2;mt++){
          int m=wm+mt*16+gid;
          af[w][mt][0]=__float_as_uint(ASI(cur,w,m  ,ks+tig  ));
          af[w][mt][1]=__float_as_uint(ASI(cur,w,m+8,ks+tig  ));
          af[w][mt][2]=__float_as_uint(ASI(cur,w,m  ,ks+tig+4));
          af[w][mt][3]=__float_as_uint(ASI(cur,w,m+8,ks+tig+4));
        }
#pragma unroll
      for(int nt=0;nt<4;nt++){
        int n=wn+nt*8+gid;
        bf[nt][0]=__float_as_uint(BSI(cur,ks+tig  ,n));
        bf[nt][1]=__float_as_uint(BSI(cur,ks+tig+4,n));
      }
#pragma unroll
      for(int w=0;w<2;w++)
#pragma unroll
        for(int mt=0;mt<2;mt++)
#pragma unroll
          for(int nt=0;nt<4;nt++)
            mma_tf32(acc[w][mt][nt], af[w][mt], bf[nt]);
    }
    if(kt<CC/GK-1){
      int nxt=cur^1;
      *(float4*)&ASI(nxt,0,aRow,aKc)   =p00;
      *(float4*)&ASI(nxt,0,aRow+64,aKc)=p01;
      *(float4*)&ASI(nxt,1,aRow,aKc)   =p10;
      *(float4*)&ASI(nxt,1,aRow+64,aKc)=p11;
      *(float4*)&BSI(nxt,bKr,bNc)      =pb;
    }
    __syncthreads();
  }
#pragma unroll
  for(int w=0;w<2;w++){
    const float* bias = w ? b1 : b0;
    float* Yb = (w ? Y1 : Y0) + (size_t)b*CC*LLEN;
#pragma unroll
    for(int mt=0;mt<2;mt++){
      int row=m0+wm+mt*16+gid;
      float bv0=bias[row], bv8=bias[row+8];
#pragma unroll
      for(int nt=0;nt<4;nt++){
        int col=l0+wn+nt*8+2*tig;
        float2 v0={acc[w][mt][nt][0]+bv0, acc[w][mt][nt][1]+bv0};
        float2 v8={acc[w][mt][nt][2]+bv8, acc[w][mt][nt][3]+bv8};
        *(float2*)(Yb+(size_t)row*LLEN+col)=v0;
        *(float2*)(Yb+(size_t)(row+8)*LLEN+col)=v8;
      }
    }
  }
}

// ---------- fused: gather cols + fsa_sel GEMM + relation + selection + fpos ----------
__global__ void __launch_bounds__(256) k_select(const float* __restrict__ f,
                                                const float* __restrict__ ksa_w,
                                                const float* __restrict__ ksa_b){
  extern __shared__ float sm[];
  float* fcols=sm;
  float* xcols=sm+9216;
  float* fsel =sm+18432;
  float* ws   =sm+27648;
  __shared__ float rel[1024];
  __shared__ float nf[32],nx[32],f2[32];
  __shared__ int im[32],ik[32],selm[NN];
  int b=blockIdx.x, tid=threadIdx.x;
  if(tid<32){ im[tid]=g_idx1[b*32+tid]; ik[tid]=g_idx2[b*32+tid]; }
  __syncthreads();
  for(int i=tid;i<256*32;i+=256){
    int c=i>>5, j=i&31;
    fcols[c*36+j]=f   [((size_t)b*CC+c)*LLEN+im[j]];
    xcols[c*36+j]=g_xr[((size_t)b*CC+c)*LLEN+ik[j]];
  }
  __syncthreads();
  {
    int m=tid;
    float acc[32];
#pragma unroll
    for(int j=0;j<32;j++) acc[j]=0.f;
    for(int c0=0;c0<CC;c0+=32){
      __syncthreads();
      for(int i=tid;i<256*32;i+=256){
        int mr=i>>5, cj=i&31;
        ws[cj*257+mr]=ksa_w[(size_t)mr*CC+c0+cj];
      }
      __syncthreads();
#pragma unroll 1
      for(int cj=0;cj<32;cj++){
        float w=ws[cj*257+m];
        const float* fr=&fcols[(c0+cj)*36];
#pragma unroll
        for(int q=0;q<8;q++){
          float4 v=*(const float4*)(fr+q*4);
          acc[q*4+0]=fmaf(w,v.x,acc[q*4+0]);
          acc[q*4+1]=fmaf(w,v.y,acc[q*4+1]);
          acc[q*4+2]=fmaf(w,v.z,acc[q*4+2]);
          acc[q*4+3]=fmaf(w,v.w,acc[q*4+3]);
        }
      }
    }
    float bv=ksa_b[m];
#pragma unroll
    for(int j=0;j<32;j++) fsel[m*36+j]=acc[j]+bv;
  }
  __syncthreads();
  if(tid<64){
    int j=tid&31;
    const float* base=(tid<32)?fsel:xcols;
    float s=0.f;
    for(int c=0;c<CC;c++){ float v=base[c*36+j]; s=fmaf(v,v,s); }
    if(tid<32) nf[j]=sqrtf(s); else nx[j]=sqrtf(s);
  }
  for(int p=tid;p<1024;p+=256){
    int m=p>>5, k=p&31;
    float s=0.f;
#pragma unroll 4
    for(int c=0;c<CC;c++) s=fmaf(fsel[c*36+m],xcols[c*36+k],s);
    rel[p]=s;
  }
  __syncthreads();
  if(tid<32){
    float mx=-INFINITY;
    for(int k=0;k<32;k++) mx=fmaxf(mx, rel[tid*32+k]/(nf[tid]*nx[k]+EPSF));
    f2[tid]=mx;
  }
  __syncthreads();
  if(tid==0){
    float mx=-INFINITY;
    for(int m=0;m<32;m++) mx=fmaxf(mx,f2[m]);
    float s=0.f;
    for(int m=0;m<32;m++){ f2[m]=__expf(f2[m]-mx); s+=f2[m]; }
    uint32_t r1k[2],r2k[2],r3k[2]; jax_subkeys(r1k,r2k,r3k);
    for(int m=0;m<32;m++){
      int j=b*32+m;
      uint32_t i=(uint32_t)(j&63),o0,o1;
      tf2x32(r3k[0],r3k[1],i,i+64u,o0,o1);
      uint32_t bits=(j<64)?o0:o1;
      f2[m]=__logf(f2[m]/s+1e-20f)+gumbel_bits(bits);
    }
    for(int j=0;j<NN;j++){
      float bv=-INFINITY; int bi=0;
      for(int m=0;m<32;m++) if(f2[m]>bv){bv=f2[m];bi=m;}
      selm[j]=bi; f2[bi]=-INFINITY;
    }
  }
  __syncthreads();
  {
    int c=tid;
#pragma unroll
    for(int j=0;j<NN;j++)
      g_fpos[((size_t)b*CC+c)*NN+j]=fsel[c*36+selm[j]];
  }
}

// ---------- fused act_pos + xn + softmax + cnt (2-way c-split, 256 thr) ----------
__global__ void __launch_bounds__(256) k_att(const float* __restrict__ x,
                                             const float* __restrict__ kn,
                                             const float* __restrict__ alpha){
  __shared__ float smu[8192];       // fp_s[4096] | kn_s[4096]; reused as part[128*36]
  __shared__ float al_s[NN];
  float* fp_s=smu;
  float* kn_s=smu+4096;
  int b=blockIdx.y, tid=threadIdx.x;
  int half=tid>>7, lt=tid&127;
  int l=blockIdx.x*128+lt;
  for(int i=tid;i<CC*NN;i+=256){
    fp_s[i]=g_fpos[(size_t)b*CC*NN+i];
    int c=i>>4, n=i&15;
    kn_s[i]=kn[n*CC+c];
  }
  if(tid<NN) al_s[tid]=fminf(fmaxf(alpha[tid],0.0f),1.0f);
  __syncthreads();
  float aa[NN],ax[NN];
#pragma unroll
  for(int n=0;n<NN;n++){aa[n]=0.f;ax[n]=0.f;}
  const float* xrp=g_xr+((size_t)b*CC+half*128)*LLEN+l;
  const float* xp =x   +((size_t)b*CC+half*128)*LLEN+l;
  const int cb=half*128;
  for(int cc=0;cc<128;cc++){
    float xrv=__ldg(xrp+(size_t)cc*LLEN);
    float xv =__ldg(xp +(size_t)cc*LLEN);
    const float4* fr=(const float4*)(fp_s+(cb+cc)*NN);
    const float4* kr=(const float4*)(kn_s+(cb+cc)*NN);
#pragma unroll
    for(int q=0;q<4;q++){
      float4 fv=fr[q], kv=kr[q];
      aa[q*4+0]=fmaf(xrv,fv.x,aa[q*4+0]);
      aa[q*4+1]=fmaf(xrv,fv.y,aa[q*4+1]);
      aa[q*4+2]=fmaf(xrv,fv.z,aa[q*4+2]);
      aa[q*4+3]=fmaf(xrv,fv.w,aa[q*4+3]);
      ax[q*4+0]=fmaf(xv ,kv.x,ax[q*4+0]);
      ax[q*4+1]=fmaf(xv ,kv.y,ax[q*4+1]);
      ax[q*4+2]=fmaf(xv ,kv.z,ax[q*4+2]);
      ax[q*4+3]=fmaf(xv ,kv.w,ax[q*4+3]);
    }
  }
  __syncthreads();   // all fp/kn reads done; reuse smu as partial buffer
  float* part=smu;   // [128][36]
  if(half==1){
#pragma unroll
    for(int n=0;n<NN;n++){ part[lt*36+n]=aa[n]; part[lt*36+16+n]=ax[n]; }
  }
  __syncthreads();
  if(half==0){
    int lane=tid&31;
#pragma unroll
    for(int n=0;n<NN;n++){ aa[n]+=part[lt*36+n]; ax[n]+=part[lt*36+16+n]; }
    float lg[NN],mx=-INFINITY;
#pragma unroll
    for(int n=0;n<NN;n++){ lg[n]=(al_s[n]*aa[n]+ax[n])*0.1f; mx=fmaxf(mx,lg[n]); }
    float s=0.f;
#pragma unroll
    for(int n=0;n<NN;n++){ lg[n]=__expf(lg[n]-mx); s+=lg[n]; }
    float inv=1.0f/s;
#pragma unroll
    for(int n=0;n<NN;n++){
      float v=lg[n]*inv;
      g_att[((size_t)b*NN+n)*LLEN+l]=v;
#pragma unroll
      for(int o=16;o;o>>=1) v+=__shfl_xor_sync(0xffffffffu,v,o);
      if(lane==0) atomicAdd(&g_cnt[b*NN+n], v);
    }
  }
}

// ---------- per-(b,c,n) weighted moments (2-way l-split, 256 thr) ----------
__global__ void __launch_bounds__(256) k_stats(){
  __shared__ float att_s[2][NN][130];
  __shared__ float xo_s[2][8][130];
  __shared__ float p1[128], p2[128];
  int b=blockIdx.y, c0=blockIdx.x*8, tid=threadIdx.x;
  int half=tid>>7, r=tid&127;
  int cr=r>>4, n=r&15;
  int lbase=half*2048;
  float s1=0.f,s2=0.f;
  for(int l0=0;l0<2048;l0+=128){
    for(int i=r;i<16*128;i+=128){
      int rr=i>>7, lc=i&127;
      att_s[half][rr][lc]=g_att[((size_t)b*NN+rr)*LLEN+lbase+l0+lc];
    }
    for(int i=r;i<8*128;i+=128){
      int rr=i>>7, lc=i&127;
      xo_s[half][rr][lc]=g_xo[((size_t)b*CC+c0+rr)*LLEN+lbase+l0+lc];
    }
    __syncthreads();
#pragma unroll 4
    for(int lc=0;lc<128;lc+=2){
      float2 xv=*(float2*)&xo_s[half][cr][lc];
      float2 av=*(float2*)&att_s[half][n][lc];
      float h0=xv.x*av.x, h1=xv.y*av.y;
      s1+=h0+h1; s2=fmaf(h0,h0,fmaf(h1,h1,s2));
    }
    __syncthreads();
  }
  if(half==1){ p1[r]=s1; p2[r]=s2; }
  __syncthreads();
  if(half==0){
    s1+=p1[r]; s2+=p2[r];
    float cnt=g_cnt[b*NN+n]+EPSF;
    float mean=s1/cnt;
    float varsum=fmaf((float)LLEN*mean,mean, s2-2.0f*mean*s1);
    float stdv=sqrtf(fmaxf(varsum,0.0f)/cnt);
    float p=1.0f/(stdv+EPSF);
    size_t o=((size_t)b*CC+c0+cr)*NN+n;
    g_P[o]=p; g_Q[o]=mean*p;
  }
}

// ---------- fused K=16 GEMMs + epilogue ----------
__global__ void __launch_bounds__(256) k_fuse(const float* __restrict__ x,
                                              const float* __restrict__ sigma,
                                              float* __restrict__ out){
  __shared__ float att_s[NN][64];
  __shared__ float P_s[16][16], Q_s[16][16];
  int b=blockIdx.z, c0=blockIdx.y*16, l0=blockIdx.x*64;
  int tid=threadIdx.x;
  for(int i=tid;i<NN*64;i+=256){
    int n=i>>6, l=i&63;
    att_s[n][l]=g_att[((size_t)b*NN+n)*LLEN+l0+l];
  }
  {
    int cl=tid>>4, n=tid&15;
    P_s[cl][n]=g_P[((size_t)b*CC+c0+cl)*NN+n];
    Q_s[cl][n]=g_Q[((size_t)b*CC+c0+cl)*NN+n];
  }
  __syncthreads();
  float sg=sigma[0];
  int ll=tid&63, cbase=tid>>6;
  for(int cc=cbase;cc<16;cc+=4){
    float r=0.f,s=0.f;
#pragma unroll
    for(int n=0;n<NN;n++){
      float a=att_s[n][ll];
      r=fmaf(P_s[cc][n],a,r);
      s=fmaf(Q_s[cc][n],a,s);
    }
    size_t o=((size_t)b*CC+c0+cc)*LLEN+l0+ll;
    out[o]=x[o]+sg*(g_xo[o]*r-s);
  }
}

extern "C" void kernel_launch(void* const* d_in, const int* in_sizes, int n_in,
                              void* d_out, int out_size){
  const float* x    =(const float*)d_in[0];
  const float* f    =(const float*)d_in[1];
  const float* mask =(const float*)d_in[2];
  const float* ksa_w=(const float*)d_in[3];
  const float* ksa_b=(const float*)d_in[4];
  const float* kr_w =(const float*)d_in[5];
  const float* kr_b =(const float*)d_in[6];
  const float* kn   =(const float*)d_in[7];
  const float* ko_w =(const float*)d_in[8];
  const float* ko_b =(const float*)d_in[9];
  const float* alpha=(const float*)d_in[10];
  const float* sigma=(const float*)d_in[11];
  float* out=(float*)d_out;

  float *xr,*xo;
  cudaGetSymbolAddress((void**)&xr ,g_xr);
  cudaGetSymbolAddress((void**)&xo ,g_xo);

  cudaFuncSetAttribute(k_gemm_dual, cudaFuncAttributeMaxDynamicSharedMemorySize, 50176);
  cudaFuncSetAttribute(k_select,    cudaFuncAttributeMaxDynamicSharedMemorySize, 143488);

  k_pre<<<9,256>>>(mask, kn, out+(out_size-1));
  dim3 gg(LLEN/GN, CC/GM, BB);
  k_gemm_dual<<<gg,256,50176>>>(kr_w,kr_b,ko_w,ko_b,x,xr,xo);
  k_select<<<BB,256,143488>>>(f,ksa_w,ksa_b);
  k_att<<<dim3(LLEN/128,BB),256>>>(x,kn,alpha);
  k_stats<<<dim3(CC/8,BB),256>>>();
  k_fuse<<<dim3(LLEN/64,CC/16,BB),256>>>(x,sigma,out);
}